// round 15
// baseline (speedup 1.0000x reference)
#include <cuda_runtime.h>
#include <cuda_bf16.h>
#include <math.h>
#include <stdint.h>

// ---------------------------------------------------------------------------
// DCNv2: B=8, C=64, H=W=128, K=3, O=64  — all-HMMA, channel-contiguous gather
//  k_prep:    weights -> m16n8k16 B-fragment order (bf16 hi/lo packed uint4)
//  k_tr:      x [c][h][w] -> g_x2 [h][w][c]  (gathers become LDG.128)
//  k_offmask: 27-ch 3x3 conv as 9 syncless shift-GEMMs (HMMA)
//  k_dcn:     per-row deformable GEMM; vectorized gathers from g_x2,
//             ping-pong A buffers, one sync per tap, coalesced epilogue.
// ---------------------------------------------------------------------------

#define Bb 8
#define HW (128*128)

__device__ float g_off [Bb * 18 * HW];
__device__ float g_mask[Bb * 9  * HW];
__device__ __align__(16) float g_x2[Bb * HW * 64];  // [b][hw][c]
__device__ __align__(16) uint4 g_Bfrag[9 * 1024];   // dcn: [k][wo2][ks4][nt4][lane32]
__device__ __align__(16) uint4 g_Wfrag[9 * 512];    // off/mask: [k][wo2][ks4][nt2][lane32]

// ---- helpers ---------------------------------------------------------------
__device__ __forceinline__ unsigned smem_u32(const void* p) {
    unsigned a;
    asm("{ .reg .u64 t; cvta.to.shared.u64 t, %1; cvt.u32.u64 %0, t; }"
        : "=r"(a) : "l"(p));
    return a;
}
__device__ __forceinline__ void ldx4(unsigned* r, unsigned addr) {
    asm volatile("ldmatrix.sync.aligned.m8n8.x4.shared.b16 {%0,%1,%2,%3}, [%4];"
                 : "=r"(r[0]), "=r"(r[1]), "=r"(r[2]), "=r"(r[3]) : "r"(addr));
}
__device__ __forceinline__ void mma_bf16(float* c, const unsigned* a,
                                         unsigned b0, unsigned b1) {
    asm volatile("mma.sync.aligned.m16n8k16.row.col.f32.bf16.bf16.f32 "
                 "{%0,%1,%2,%3}, {%4,%5,%6,%7}, {%8,%9}, {%0,%1,%2,%3};"
                 : "+f"(c[0]), "+f"(c[1]), "+f"(c[2]), "+f"(c[3])
                 : "r"(a[0]), "r"(a[1]), "r"(a[2]), "r"(a[3]), "r"(b0), "r"(b1));
}
__device__ __forceinline__ int swz(int off) { return off ^ ((off >> 3) & 0x70); }

// packed bf16 hi/lo split: {s1,s0} -> hi u32 (s1 in high half), lo u32
__device__ __forceinline__ void split2(float s0, float s1, unsigned& hi, unsigned& lo) {
    unsigned h;
    asm("cvt.rn.bf16x2.f32 %0, %1, %2;" : "=r"(h) : "f"(s1), "f"(s0));
    const float h0f = __uint_as_float(h << 16);
    const float h1f = __uint_as_float(h & 0xFFFF0000u);
    unsigned l;
    asm("cvt.rn.bf16x2.f32 %0, %1, %2;" : "=r"(l) : "f"(s1 - h1f), "f"(s0 - h0f));
    hi = h; lo = l;
}

// ---- k_prep: weights -> MMA B-fragment order -------------------------------
__global__ void k_prep(const float* __restrict__ w_dcn,
                       const float* __restrict__ w_off,
                       const float* __restrict__ w_mask) {
    int gi = blockIdx.x * 256 + threadIdx.x;
    if (gi < 9 * 1024) {
        int lane = gi & 31;
        int nt = (gi >> 5) & 3, ks = (gi >> 7) & 3, wo = (gi >> 9) & 1, tap = gi >> 10;
        int o = wo * 32 + nt * 8 + (lane >> 2);
        int c = ks * 16 + 2 * (lane & 3);
        unsigned h0, l0, h1, l1;
        split2(w_dcn[((o << 6) + c) * 9 + tap],
               w_dcn[((o << 6) + c + 1) * 9 + tap], h0, l0);
        split2(w_dcn[((o << 6) + c + 8) * 9 + tap],
               w_dcn[((o << 6) + c + 9) * 9 + tap], h1, l1);
        g_Bfrag[gi] = make_uint4(h0, h1, l0, l1);
    } else if (gi < 9 * 1024 + 9 * 512) {
        int gj = gi - 9 * 1024;
        int lane = gj & 31;
        int nt = (gj >> 5) & 1, ks = (gj >> 6) & 3, wo = (gj >> 8) & 1, tap = gj >> 9;
        int o = wo * 16 + nt * 8 + (lane >> 2);
        int c = ks * 16 + 2 * (lane & 3);
        float v[4];
#pragma unroll
        for (int u = 0; u < 4; u++) {
            int cc = c + (u >> 1) * 8 + (u & 1);
            v[u] = (o < 18) ? w_off[(o * 64 + cc) * 9 + tap]
                 : (o < 27) ? w_mask[((o - 18) * 64 + cc) * 9 + tap] : 0.f;
        }
        unsigned h0, l0, h1, l1;
        split2(v[0], v[1], h0, l0);
        split2(v[2], v[3], h1, l1);
        g_Wfrag[gj] = make_uint4(h0, h1, l0, l1);
    }
}

// ---- k_tr: x [c][h][w] -> [h][w][c] ----------------------------------------
// grid: 8*256 blocks (64 pixels each), 256 threads
__global__ __launch_bounds__(256)
void k_tr(const float* __restrict__ x) {
    __shared__ float t[64][65];
    const int b = blockIdx.x >> 8;
    const int p0 = (blockIdx.x & 255) << 6;
    const float* xb = x + (b << 20);
    const int tid = threadIdx.x;
    const int r = tid >> 6, q = tid & 63;
#pragma unroll
    for (int i = 0; i < 16; i++) {
        const int c = (i << 2) + r;
        t[q][c] = xb[(c << 14) + p0 + q];
    }
    __syncthreads();
    float* ob = g_x2 + (b << 20) + (p0 << 6);
#pragma unroll
    for (int i = 0; i < 16; i++) {
        const int p = (i << 2) + r;
        ob[(p << 6) + q] = t[p][q];
    }
}

// ---- k_offmask: 3x3 conv as 9 syncless shift-GEMMs -------------------------
#define OM_TILE 16640
#define SMEM_OM (6 * OM_TILE + 1024)

__global__ __launch_bounds__(256)
void k_offmask(const float* __restrict__ x,
               const float* __restrict__ b_off,
               const float* __restrict__ b_mask) {
    __shared__ float sbias[32];
    extern __shared__ char dsm0[];
    char* base = (char*)((((uintptr_t)dsm0) + 1023) & ~(uintptr_t)1023);
    const unsigned u_base = smem_u32(base);

    const int tid = threadIdx.x;
    const int lane = tid & 31, wid = tid >> 5;
    const int b = blockIdx.x >> 7;
    const int h = blockIdx.x & 127;
    const int hw0 = h << 7;
    const float* xb = x + (b << 20);

    if (tid < 32)
        sbias[tid] = (tid < 18) ? b_off[tid] : ((tid < 27) ? b_mask[tid - 18] : 0.f);

    if (tid < 96) {
        int r = tid >> 3;
        int ts = r >> 1;
        int row = (r & 1) ? 129 : 0;
        int addr = ts * OM_TILE + swz(row * 128 + ((tid & 7) << 4));
        *(uint4*)(base + addr) = make_uint4(0, 0, 0, 0);
    }
#pragma unroll 1
    for (int it = 0; it < 12; it++) {
        int T = wid + (it << 3);
        int di = T >> 5;
        int rem = T & 31;
        int cg = rem >> 2, wq = rem & 3;
        int w = (wq << 5) + lane;
        int gy = h - 1 + di;
        float v[8];
        if ((unsigned)gy < 128u) {
            const float* xp = xb + ((cg * 8) << 14) + (gy << 7) + w;
#pragma unroll
            for (int j = 0; j < 8; j++) v[j] = xp[j << 14];
        } else {
#pragma unroll
            for (int j = 0; j < 8; j++) v[j] = 0.f;
        }
        unsigned wh[4], wl[4];
#pragma unroll
        for (int u = 0; u < 4; u++) split2(v[2 * u], v[2 * u + 1], wh[u], wl[u]);
        int addr = swz((w + 1) * 128 + (cg << 4));
        *(uint4*)(base + di * OM_TILE + addr) = make_uint4(wh[0], wh[1], wh[2], wh[3]);
        *(uint4*)(base + (3 + di) * OM_TILE + addr) = make_uint4(wl[0], wl[1], wl[2], wl[3]);
    }
    __syncthreads();

    const int wp = wid >> 1, wo = wid & 1;
    const int m0 = wp << 5, o0 = wo << 4;
    const int as = lane >> 3;
    const int arl = (lane & 7) + ((as & 1) << 3);
    const int akc = as >> 1;

    float C[2][2][4];
#pragma unroll
    for (int i = 0; i < 2; i++)
#pragma unroll
        for (int j = 0; j < 2; j++)
#pragma unroll
            for (int q = 0; q < 4; q++) C[i][j][q] = 0.f;

#pragma unroll 1
    for (int t = 0; t < 9; t++) {
        const int di = t / 3, dj = t - 3 * di;
        const unsigned tHi = u_base + di * OM_TILE;
        const unsigned tLo = u_base + (3 + di) * OM_TILE;
        const uint4* bk = g_Wfrag + ((t * 2 + wo) << 8) + lane;
#pragma unroll
        for (int ks = 0; ks < 4; ks++) {
            uint4 bf[2];
#pragma unroll
            for (int nt = 0; nt < 2; nt++) bf[nt] = bk[(ks * 2 + nt) << 5];
#pragma unroll
            for (int mt = 0; mt < 2; mt++) {
                unsigned Af[4], Alf[4];
                const unsigned ad =
                    swz((m0 + mt * 16 + arl + dj) * 128 + (ks * 2 + akc) * 16);
                ldx4(Af, tHi + ad);
                ldx4(Alf, tLo + ad);
#pragma unroll
                for (int nt = 0; nt < 2; nt++) {
                    mma_bf16(C[mt][nt], Af, bf[nt].x, bf[nt].y);
                    mma_bf16(C[mt][nt], Af, bf[nt].z, bf[nt].w);
                    mma_bf16(C[mt][nt], Alf, bf[nt].x, bf[nt].y);
                }
            }
        }
    }
    __syncthreads();

    float* S = (float*)base;
    const int prow = lane >> 2;
    const int oc = 2 * (lane & 3);
#pragma unroll
    for (int mt = 0; mt < 2; mt++)
#pragma unroll
        for (int nt = 0; nt < 2; nt++)
#pragma unroll
            for (int q = 0; q < 4; q++) {
                const int p = m0 + mt * 16 + prow + ((q >> 1) << 3);
                const int ch = o0 + nt * 8 + oc + (q & 1);
                S[ch * 132 + p] = C[mt][nt][q] + sbias[ch];
            }
    __syncthreads();
#pragma unroll
    for (int j = 0; j < 4; j++) {
        const int idx = j * 256 + tid;
        if (idx < 27 * 32) {
            const int ch = idx >> 5, p4 = idx & 31;
            float4 v = *(float4*)(S + ch * 132 + p4 * 4);
            if (ch < 18) {
                *(float4*)(g_off + (b * 18 + ch) * HW + hw0 + p4 * 4) = v;
            } else {
                v.x = 1.f / (1.f + expf(-v.x));
                v.y = 1.f / (1.f + expf(-v.y));
                v.z = 1.f / (1.f + expf(-v.z));
                v.w = 1.f / (1.f + expf(-v.w));
                *(float4*)(g_mask + (b * 9 + ch - 18) * HW + hw0 + p4 * 4) = v;
            }
        }
    }
}

// ---- k_dcn: deformable GEMM, vectorized gathers ----------------------------
// grid: 1024 blocks (b*128 rows), 256 threads (8 warps: 4 in p x 2 in o)
#define SMEM2 (65536 + 1024)

__global__ __launch_bounds__(256, 2)
void k_dcn(const float* __restrict__ b_dcn, float* __restrict__ out) {
    __shared__ float sbias[64];
    extern __shared__ char dsm[];
    char* dgen = (char*)((((uintptr_t)dsm) + 1023) & ~(uintptr_t)1023);
    const unsigned uA = smem_u32(dgen);

    const int tid = threadIdx.x;
    const int wid = tid >> 5, lane = tid & 31;
    const int b = blockIdx.x >> 7;
    const int h = blockIdx.x & 127;
    const int hw0 = h << 7;
    const float4* xp2 = (const float4*)(g_x2 + (b << 20));  // [hw][16 float4]

    if (tid < 64) sbias[tid] = b_dcn[tid];

    const int wp = wid >> 1, wo = wid & 1;
    const int m0 = wp << 5, o0 = wo << 5;
    const int as = lane >> 3;
    const int arl = (lane & 7) + ((as & 1) << 3);
    const int akc = as >> 1;

    float C[2][4][4];
#pragma unroll
    for (int i = 0; i < 2; i++)
#pragma unroll
        for (int j = 0; j < 4; j++)
#pragma unroll
            for (int q = 0; q < 4; q++) C[i][j][q] = 0.f;

    const int ps = tid & 127;     // sampling pixel (dup across halves)
    const int c0 = tid >> 7;      // channel half

#pragma unroll 1
    for (int k = 0; k < 9; k++) {
        const float dy = g_off[(b * 18 + 2 * k) * HW + hw0 + ps];
        const float dx = g_off[(b * 18 + 2 * k + 1) * HW + hw0 + ps];
        const float m  = g_mask[(b * 9 + k) * HW + hw0 + ps];
        const float py = (float)(h - 1 + k / 3) + dy;
        const float px = (float)(ps - 1 + k % 3) + dx;
        const float y0f = floorf(py), x0f = floorf(px);
        const float wy1 = py - y0f, wx1 = px - x0f;
        const float wy0 = 1.f - wy1, wx0 = 1.f - wx1;
        const int y0 = (int)y0f, x0 = (int)x0f;
        const int y1 = y0 + 1,  x1 = x0 + 1;
        const float vy0 = ((unsigned)y0 < 128u) ? 1.f : 0.f;
        const float vy1 = ((unsigned)y1 < 128u) ? 1.f : 0.f;
        const float vx0 = ((unsigned)x0 < 128u) ? 1.f : 0.f;
        const float vx1 = ((unsigned)x1 < 128u) ? 1.f : 0.f;
        const int y0c = min(max(y0, 0), 127), y1c = min(max(y1, 0), 127);
        const int x0c = min(max(x0, 0), 127), x1c = min(max(x1, 0), 127);
        const float W00 = wy0 * wx0 * m * vy0 * vx0;
        const float W01 = wy0 * wx1 * m * vy0 * vx1;
        const float W10 = wy1 * wx0 * m * vy1 * vx0;
        const float W11 = wy1 * wx1 * m * vy1 * vx1;
        const int a00 = ((y0c << 7) + x0c) << 4, a01 = ((y0c << 7) + x1c) << 4;
        const int a10 = ((y1c << 7) + x0c) << 4, a11 = ((y1c << 7) + x1c) << 4;

        // sample 32 channels (8 per group) with LDG.128 gathers
        char* Abuf = dgen + ((k & 1) << 15);
#pragma unroll
        for (int g = 0; g < 4; g++) {
            const int cq = (c0 << 3) + (g << 1);
            unsigned wh[4], wl[4];
#pragma unroll
            for (int u = 0; u < 2; u++) {
                const float4 v00 = xp2[a00 + cq + u];
                const float4 v01 = xp2[a01 + cq + u];
                const float4 v10 = xp2[a10 + cq + u];
                const float4 v11 = xp2[a11 + cq + u];
                const float s0 = W00 * v00.x + W01 * v01.x + W10 * v10.x + W11 * v11.x;
                const float s1 = W00 * v00.y + W01 * v01.y + W10 * v10.y + W11 * v11.y;
                const float s2 = W00 * v00.z + W01 * v01.z + W10 * v10.z + W11 * v11.z;
                const float s3 = W00 * v00.w + W01 * v01.w + W10 * v10.w + W11 * v11.w;
                split2(s0, s1, wh[2 * u], wl[2 * u]);
                split2(s2, s3, wh[2 * u + 1], wl[2 * u + 1]);
            }
            const int addr = swz((ps << 7) + (c0 << 6) + (g << 4));
            *(uint4*)(Abuf + addr) = make_uint4(wh[0], wh[1], wh[2], wh[3]);
            *(uint4*)(Abuf + 16384 + addr) = make_uint4(wl[0], wl[1], wl[2], wl[3]);
        }
        __syncthreads();   // the ONLY sync per tap

        const unsigned aH = uA + ((k & 1) << 15);
        const unsigned aL = aH + 16384;
        const uint4* bk = g_Bfrag + ((k * 2 + wo) << 9) + lane;
#pragma unroll
        for (int ks = 0; ks < 4; ks++) {
            uint4 bf[4];
#pragma unroll
            for (int nt = 0; nt < 4; nt++) bf[nt] = bk[(ks * 4 + nt) << 5];
#pragma unroll
            for (int mt = 0; mt < 2; mt++) {
                unsigned Af[4], Alf[4];
                const unsigned ad =
                    swz((m0 + mt * 16 + arl) * 128 + (ks * 2 + akc) * 16);
                ldx4(Af, aH + ad);
                ldx4(Alf, aL + ad);
#pragma unroll
                for (int nt = 0; nt < 4; nt++) {
                    mma_bf16(C[mt][nt], Af, bf[nt].x, bf[nt].y);
                    mma_bf16(C[mt][nt], Af, bf[nt].z, bf[nt].w);
                    mma_bf16(C[mt][nt], Alf, bf[nt].x, bf[nt].y);
                }
            }
        }
    }

    // epilogue: transpose to S[64o][132p] (+bias), then coalesced stores
    __syncthreads();
    float* S = (float*)dgen;
    const int prow = lane >> 2;
    const int oc = 2 * (lane & 3);
#pragma unroll
    for (int mt = 0; mt < 2; mt++)
#pragma unroll
        for (int nt = 0; nt < 4; nt++)
#pragma unroll
            for (int q = 0; q < 4; q++) {
                const int p = m0 + mt * 16 + prow + ((q >> 1) << 3);
                const int o = o0 + nt * 8 + oc + (q & 1);
                S[o * 132 + p] = C[mt][nt][q] + sbias[o];
            }
    __syncthreads();
    float* ob = out + (b << 20) + hw0;
#pragma unroll
    for (int j = 0; j < 8; j++) {
        const int f4 = j * 256 + tid;
        const int o = f4 >> 5, p4 = f4 & 31;
        *(float4*)(ob + (o << 14) + p4 * 4) = *(float4*)(S + o * 132 + p4 * 4);
    }
}

// ---------------------------------------------------------------------------
extern "C" void kernel_launch(void* const* d_in, const int* in_sizes, int n_in,
                              void* d_out, int out_size) {
    const float* x      = (const float*)d_in[0];
    const float* w_off  = (const float*)d_in[1];
    const float* b_off  = (const float*)d_in[2];
    const float* w_mask = (const float*)d_in[3];
    const float* b_mask = (const float*)d_in[4];
    const float* w_dcn  = (const float*)d_in[5];
    const float* b_dcn  = (const float*)d_in[6];
    float* out = (float*)d_out;

    cudaFuncSetAttribute(k_offmask, cudaFuncAttributeMaxDynamicSharedMemorySize, SMEM_OM);
    cudaFuncSetAttribute(k_dcn,     cudaFuncAttributeMaxDynamicSharedMemorySize, SMEM2);

    k_prep<<<(9 * 1024 + 9 * 512 + 255) / 256, 256>>>(w_dcn, w_off, w_mask);
    k_tr<<<Bb * 256, 256>>>(x);
    k_offmask<<<Bb * 128, 256, SMEM_OM>>>(x, b_off, b_mask);
    k_dcn<<<Bb * 128, 256, SMEM2>>>(b_dcn, out);
}

// round 16
// speedup vs baseline: 1.9233x; 1.9233x over previous
#include <cuda_runtime.h>
#include <cuda_bf16.h>
#include <math.h>
#include <stdint.h>

// ---------------------------------------------------------------------------
// DCNv2: B=8, C=64, H=W=128, K=3, O=64  — single-pass TF32 HMMA version
//  k_prep:    weights -> m16n8k8 tf32 B-fragment order (uint4 = 2 k-chunks)
//  k_offmask: 27-ch 3x3 conv as 9 syncless shift-GEMMs (tf32)
//  k_dcn:     per-row deformable GEMM; coalesced scalar gathers ([c][h][w]),
//             pad-68 fp32/tf32 A tiles + LDS-frag loads, ping-pong buffers,
//             one sync per tap, coalesced epilogue.
// ---------------------------------------------------------------------------

#define Bb 8
#define HW (128*128)

__device__ float g_off [Bb * 18 * HW];
__device__ float g_mask[Bb * 9  * HW];
__device__ __align__(16) uint4 g_Bfrag[9 * 1024];  // dcn: [k][wo2][kk4][nt4][lane32]
__device__ __align__(16) uint4 g_Wfrag[9 * 512];   // off/mask: [k][wo2][kk4][nt2][lane32]

// ---- helpers ---------------------------------------------------------------
__device__ __forceinline__ unsigned tf32c(float f) {
    unsigned r;
    asm("cvt.rna.tf32.f32 %0, %1;" : "=r"(r) : "f"(f));
    return r;
}
__device__ __forceinline__ void mma_tf32(float* c, const unsigned* a,
                                         unsigned b0, unsigned b1) {
    asm volatile("mma.sync.aligned.m16n8k8.row.col.f32.tf32.tf32.f32 "
                 "{%0,%1,%2,%3}, {%4,%5,%6,%7}, {%8,%9}, {%0,%1,%2,%3};"
                 : "+f"(c[0]), "+f"(c[1]), "+f"(c[2]), "+f"(c[3])
                 : "r"(a[0]), "r"(a[1]), "r"(a[2]), "r"(a[3]), "r"(b0), "r"(b1));
}

// ---- k_prep: weights -> tf32 MMA B-fragment order --------------------------
// m16n8k8 B frag (col): b0 = W[n=lane/4][k0 + lane%4], b1 = W[n][k0+4+lane%4]
// uint4 packs chunks 2kk (.x,.y) and 2kk+1 (.z,.w);  k0(chunk) = 8*chunk
__global__ void k_prep(const float* __restrict__ w_dcn,
                       const float* __restrict__ w_off,
                       const float* __restrict__ w_mask) {
    int gi = blockIdx.x * 256 + threadIdx.x;
    if (gi < 9 * 1024) {
        int lane = gi & 31;
        int nt = (gi >> 5) & 3, kk = (gi >> 7) & 3, wo = (gi >> 9) & 1, tap = gi >> 10;
        int o = wo * 32 + nt * 8 + (lane >> 2);
        int c = kk * 16 + (lane & 3);
        const float* wp = w_dcn + (o << 6) * 9 + tap;
        g_Bfrag[gi] = make_uint4(tf32c(wp[c * 9]),        tf32c(wp[(c + 4) * 9]),
                                 tf32c(wp[(c + 8) * 9]),  tf32c(wp[(c + 12) * 9]));
    } else if (gi < 9 * 1024 + 9 * 512) {
        int gj = gi - 9 * 1024;
        int lane = gj & 31;
        int nt = (gj >> 5) & 1, kk = (gj >> 6) & 3, wo = (gj >> 8) & 1, tap = gj >> 9;
        int o = wo * 16 + nt * 8 + (lane >> 2);
        int c = kk * 16 + (lane & 3);
        unsigned v[4];
#pragma unroll
        for (int u = 0; u < 4; u++) {
            int cc = c + u * 4;
            float f = (o < 18) ? w_off[(o * 64 + cc) * 9 + tap]
                    : (o < 27) ? w_mask[((o - 18) * 64 + cc) * 9 + tap] : 0.f;
            v[u] = tf32c(f);
        }
        g_Wfrag[gj] = make_uint4(v[0], v[1], v[2], v[3]);
    }
}

// ---- k_offmask: 3x3 conv as 9 syncless shift-GEMMs (tf32) ------------------
// grid: 1024 blocks (b*128 rows), 256 threads (8 warps: 4 in p x 2 in o)
// smem: 3 x-tiles [130 rows][68 floats] tf32
#define OMT_F 8840                     // 130*68 floats per tile
#define OMT_B (OMT_F * 4)
#define SMEM_OM (3 * OMT_B + 1024)

__global__ __launch_bounds__(256)
void k_offmask(const float* __restrict__ x,
               const float* __restrict__ b_off,
               const float* __restrict__ b_mask) {
    __shared__ float sbias[32];
    extern __shared__ char dsm0[];
    float* tiles = (float*)((((uintptr_t)dsm0) + 1023) & ~(uintptr_t)1023);

    const int tid = threadIdx.x;
    const int lane = tid & 31, wid = tid >> 5;
    const int b = blockIdx.x >> 7;
    const int h = blockIdx.x & 127;
    const int hw0 = h << 7;
    const float* xb = x + (b << 20);

    if (tid < 32)
        sbias[tid] = (tid < 18) ? b_off[tid] : ((tid < 27) ? b_mask[tid - 18] : 0.f);

    // zero edge rows (w' = 0 and 129) of all 3 tiles
    if (tid < 96) {
        int t3 = tid >> 5, rem = tid & 31;
        int row = (rem >> 4) ? 129 : 0, q = rem & 15;
        *(uint4*)(tiles + t3 * OMT_F + row * 68 + q * 4) = make_uint4(0, 0, 0, 0);
    }
    // stage x rows h-1..h+1 into tiles (row = w+1, col c), tf32
#pragma unroll
    for (int it = 0; it < 2; it++) {
        int T = tid + (it << 8);
        if (T < 384) {
            int di = T >> 7, w = T & 127;
            int gy = h - 1 + di;
            float* dst = tiles + di * OMT_F + (w + 1) * 68;
            if ((unsigned)gy < 128u) {
                const float* xp = xb + (gy << 7) + w;
#pragma unroll
                for (int cg = 0; cg < 16; cg++) {
                    uint4 v;
                    v.x = tf32c(xp[(cg * 4 + 0) << 14]);
                    v.y = tf32c(xp[(cg * 4 + 1) << 14]);
                    v.z = tf32c(xp[(cg * 4 + 2) << 14]);
                    v.w = tf32c(xp[(cg * 4 + 3) << 14]);
                    *(uint4*)(dst + cg * 4) = v;
                }
            } else {
#pragma unroll
                for (int cg = 0; cg < 16; cg++)
                    *(uint4*)(dst + cg * 4) = make_uint4(0, 0, 0, 0);
            }
        }
    }
    __syncthreads();

    // warp tiles: 32p x 16o
    const int wp = wid >> 1, wo = wid & 1;
    const int m0 = wp << 5, o0 = wo << 4;
    const int r = lane >> 2, t = lane & 3;

    float C[2][2][4];
#pragma unroll
    for (int i = 0; i < 2; i++)
#pragma unroll
        for (int j = 0; j < 2; j++)
#pragma unroll
            for (int q = 0; q < 4; q++) C[i][j][q] = 0.f;

#pragma unroll 1
    for (int tp = 0; tp < 9; tp++) {
        const int di = tp / 3, dj = tp - 3 * di;
        const unsigned* tl = (const unsigned*)(tiles + di * OMT_F);
        const uint4* bk = g_Wfrag + ((tp * 2 + wo) << 8) + lane;
#pragma unroll
        for (int kk = 0; kk < 4; kk++) {
            uint4 bf[2];
#pragma unroll
            for (int nt = 0; nt < 2; nt++) bf[nt] = bk[(kk * 2 + nt) << 5];
#pragma unroll
            for (int mt = 0; mt < 2; mt++) {
                const unsigned* ap = tl + (m0 + mt * 16 + r + dj) * 68 + kk * 16 + t;
                unsigned A0[4], A1[4];
                A0[0] = ap[0];  A0[1] = ap[8 * 68];
                A0[2] = ap[4];  A0[3] = ap[8 * 68 + 4];
                A1[0] = ap[8];  A1[1] = ap[8 * 68 + 8];
                A1[2] = ap[12]; A1[3] = ap[8 * 68 + 12];
#pragma unroll
                for (int nt = 0; nt < 2; nt++) {
                    mma_tf32(C[mt][nt], A0, bf[nt].x, bf[nt].y);
                    mma_tf32(C[mt][nt], A1, bf[nt].z, bf[nt].w);
                }
            }
        }
    }
    __syncthreads();

    // transpose to S[32ch][132] then coalesced stores (+bias, sigmoid on mask)
    float* S = tiles;
    const int prow = lane >> 2;
    const int oc = 2 * (lane & 3);
#pragma unroll
    for (int mt = 0; mt < 2; mt++)
#pragma unroll
        for (int nt = 0; nt < 2; nt++)
#pragma unroll
            for (int q = 0; q < 4; q++) {
                const int p = m0 + mt * 16 + prow + ((q >> 1) << 3);
                const int ch = o0 + nt * 8 + oc + (q & 1);
                S[ch * 132 + p] = C[mt][nt][q] + sbias[ch];
            }
    __syncthreads();
#pragma unroll
    for (int j = 0; j < 4; j++) {
        const int idx = j * 256 + tid;
        if (idx < 27 * 32) {
            const int ch = idx >> 5, p4 = idx & 31;
            float4 v = *(float4*)(S + ch * 132 + p4 * 4);
            if (ch < 18) {
                *(float4*)(g_off + (b * 18 + ch) * HW + hw0 + p4 * 4) = v;
            } else {
                v.x = 1.f / (1.f + expf(-v.x));
                v.y = 1.f / (1.f + expf(-v.y));
                v.z = 1.f / (1.f + expf(-v.z));
                v.w = 1.f / (1.f + expf(-v.w));
                *(float4*)(g_mask + (b * 9 + ch - 18) * HW + hw0 + p4 * 4) = v;
            }
        }
    }
}

// ---- k_dcn: tf32 deformable GEMM, one sync per tap -------------------------
// grid: 1024 blocks (b*128 rows), 256 threads (8 warps: 4 in p x 2 in o)
// dyn smem: ping-pong A buffers [128p][68 floats] = 34816 B each
#define ABUF_B 34816
#define SMEM2 (2 * ABUF_B + 1024)

__global__ __launch_bounds__(256, 2)
void k_dcn(const float* __restrict__ x,
           const float* __restrict__ b_dcn,
           float* __restrict__ out) {
    __shared__ float sbias[64];
    extern __shared__ char dsm[];
    char* dgen = (char*)((((uintptr_t)dsm) + 1023) & ~(uintptr_t)1023);

    const int tid = threadIdx.x;
    const int wid = tid >> 5, lane = tid & 31;
    const int b = blockIdx.x >> 7;
    const int h = blockIdx.x & 127;
    const int hw0 = h << 7;
    const float* xb = x + (b << 20);

    if (tid < 64) sbias[tid] = b_dcn[tid];

    // warp tiles: 32p x 32o
    const int wp = wid >> 1, wo = wid & 1;
    const int m0 = wp << 5, o0 = wo << 5;
    const int r = lane >> 2, t = lane & 3;

    float C[2][4][4];
#pragma unroll
    for (int i = 0; i < 2; i++)
#pragma unroll
        for (int j = 0; j < 4; j++)
#pragma unroll
            for (int q = 0; q < 4; q++) C[i][j][q] = 0.f;

    const int ps = tid & 127;     // sampling pixel (dup across halves)
    const int c0 = tid >> 7;      // channel half

#pragma unroll 1
    for (int k = 0; k < 9; k++) {
        // bilinear params (local, no sync)
        const float dy = g_off[(b * 18 + 2 * k) * HW + hw0 + ps];
        const float dx = g_off[(b * 18 + 2 * k + 1) * HW + hw0 + ps];
        const float m  = g_mask[(b * 9 + k) * HW + hw0 + ps];
        const float py = (float)(h - 1 + k / 3) + dy;
        const float px = (float)(ps - 1 + k % 3) + dx;
        const float y0f = floorf(py), x0f = floorf(px);
        const float wy1 = py - y0f, wx1 = px - x0f;
        const float wy0 = 1.f - wy1, wx0 = 1.f - wx1;
        const int y0 = (int)y0f, x0 = (int)x0f;
        const int y1 = y0 + 1,  x1 = x0 + 1;
        const float vy0 = ((unsigned)y0 < 128u) ? 1.f : 0.f;
        const float vy1 = ((unsigned)y1 < 128u) ? 1.f : 0.f;
        const float vx0 = ((unsigned)x0 < 128u) ? 1.f : 0.f;
        const float vx1 = ((unsigned)x1 < 128u) ? 1.f : 0.f;
        const int y0c = min(max(y0, 0), 127), y1c = min(max(y1, 0), 127);
        const int x0c = min(max(x0, 0), 127), x1c = min(max(x1, 0), 127);
        const float W00 = wy0 * wx0 * m * vy0 * vx0;
        const float W01 = wy0 * wx1 * m * vy0 * vx1;
        const float W10 = wy1 * wx0 * m * vy1 * vx0;
        const float W11 = wy1 * wx1 * m * vy1 * vx1;
        const int o00 = (y0c << 7) + x0c, o01 = (y0c << 7) + x1c;
        const int o10 = (y1c << 7) + x0c, o11 = (y1c << 7) + x1c;

        // sample 32 channels into ping-pong buffer (pad-68, conflict-free STS)
        float* Abuf = (float*)(dgen + (k & 1) * ABUF_B);
#pragma unroll
        for (int g = 0; g < 8; g++) {
            const int c = (c0 << 5) + (g << 2);
            const float* pc = xb + (c << 14);
            uint4 v;
            {
                const float s0 = W00 * pc[o00] + W01 * pc[o01]
                               + W10 * pc[o10] + W11 * pc[o11];
                v.x = tf32c(s0);
            }
            {
                const float* p1 = pc + HW;
                const float s1 = W00 * p1[o00] + W01 * p1[o01]
                               + W10 * p1[o10] + W11 * p1[o11];
                v.y = tf32c(s1);
            }
            {
                const float* p2 = pc + 2 * HW;
                const float s2 = W00 * p2[o00] + W01 * p2[o01]
                               + W10 * p2[o10] + W11 * p2[o11];
                v.z = tf32c(s2);
            }
            {
                const float* p3 = pc + 3 * HW;
                const float s3 = W00 * p3[o00] + W01 * p3[o01]
                               + W10 * p3[o10] + W11 * p3[o11];
                v.w = tf32c(s3);
            }
            *(uint4*)(Abuf + ps * 68 + c) = v;
        }
        __syncthreads();   // the ONLY sync per tap

        // GEMM: C[32p x 32o] += S[32p x 64c] * W[32o x 64c]^T (tf32)
        const unsigned* Ab = (const unsigned*)(dgen + (k & 1) * ABUF_B);
        const uint4* bk = g_Bfrag + ((k * 2 + wo) << 9) + lane;
#pragma unroll
        for (int kk = 0; kk < 4; kk++) {
            uint4 bf[4];
#pragma unroll
            for (int nt = 0; nt < 4; nt++) bf[nt] = bk[(kk * 4 + nt) << 5];
#pragma unroll
            for (int mt = 0; mt < 2; mt++) {
                const unsigned* ap = Ab + (m0 + mt * 16 + r) * 68 + kk * 16 + t;
                unsigned A0[4], A1[4];
                A0[0] = ap[0];  A0[1] = ap[8 * 68];
                A0[2] = ap[4];  A0[3] = ap[8 * 68 + 4];
                A1[0] = ap[8];  A1[1] = ap[8 * 68 + 8];
                A1[2] = ap[12]; A1[3] = ap[8 * 68 + 12];
#pragma unroll
                for (int nt = 0; nt < 4; nt++) {
                    mma_tf32(C[mt][nt], A0, bf[nt].x, bf[nt].y);
                    mma_tf32(C[mt][nt], A1, bf[nt].z, bf[nt].w);
                }
            }
        }
        __syncthreads();   // buffer reuse guard (2-deep ping-pong, cheap)
    }

    // epilogue: transpose to S[64o][132p] (+bias), then coalesced stores
    float* S = (float*)dgen;
    const int prow = lane >> 2;
    const int oc = 2 * (lane & 3);
#pragma unroll
    for (int mt = 0; mt < 2; mt++)
#pragma unroll
        for (int nt = 0; nt < 4; nt++)
#pragma unroll
            for (int q = 0; q < 4; q++) {
                const int p = m0 + mt * 16 + prow + ((q >> 1) << 3);
                const int o = o0 + nt * 8 + oc + (q & 1);
                S[o * 132 + p] = C[mt][nt][q] + sbias[o];
            }
    __syncthreads();
    float* ob = out + (b << 20) + hw0;
#pragma unroll
    for (int j = 0; j < 8; j++) {
        const int f4 = j * 256 + tid;
        const int o = f4 >> 5, p4 = f4 & 31;
        *(float4*)(ob + (o << 14) + p4 * 4) = *(float4*)(S + o * 132 + p4 * 4);
    }
}

// ---------------------------------------------------------------------------
extern "C" void kernel_launch(void* const* d_in, const int* in_sizes, int n_in,
                              void* d_out, int out_size) {
    const float* x      = (const float*)d_in[0];
    const float* w_off  = (const float*)d_in[1];
    const float* b_off  = (const float*)d_in[2];
    const float* w_mask = (const float*)d_in[3];
    const float* b_mask = (const float*)d_in[4];
    const float* w_dcn  = (const float*)d_in[5];
    const float* b_dcn  = (const float*)d_in[6];
    float* out = (float*)d_out;

    cudaFuncSetAttribute(k_offmask, cudaFuncAttributeMaxDynamicSharedMemorySize, SMEM_OM);
    cudaFuncSetAttribute(k_dcn,     cudaFuncAttributeMaxDynamicSharedMemorySize, SMEM2);

    k_prep<<<(9 * 1024 + 9 * 512 + 255) / 256, 256>>>(w_dcn, w_off, w_mask);
    k_offmask<<<Bb * 128, 256, SMEM_OM>>>(x, b_off, b_mask);
    k_dcn<<<Bb * 128, 256, SMEM2>>>(x, b_dcn, out);
}

// round 17
// speedup vs baseline: 1.9620x; 1.0201x over previous
#include <cuda_runtime.h>
#include <cuda_bf16.h>
#include <math.h>
#include <stdint.h>

// ---------------------------------------------------------------------------
// DCNv2: B=8, C=64, H=W=128, K=3, O=64  — fused single-pass TF32 HMMA
//  k_prep: weights -> m16n8k8 tf32 B-fragment order (uint4 = 2 k-chunks)
//  k_main: per-row block (b,h):
//    phase A: 27-ch 3x3 conv as 9 syncless shift-GEMMs -> off/mask in SMEM
//    phase B: deformable GEMM; coalesced scalar gathers, pad-68 tf32 A tiles,
//             ping-pong buffers, ONE sync per tap, coalesced epilogue.
//  SMEM overlay: conv tiles (106KB) -> [ping-pong A 68KB | S_om 14KB]
// ---------------------------------------------------------------------------

#define Bb 8
#define HW (128*128)

__device__ __align__(16) uint4 g_Bfrag[9 * 1024];  // dcn: [k][wo2][kk4][nt4][lane32]
__device__ __align__(16) uint4 g_Wfrag[9 * 512];   // off/mask: [k][wo2][kk4][nt2][lane32]

// ---- helpers ---------------------------------------------------------------
__device__ __forceinline__ unsigned tf32c(float f) {
    unsigned r;
    asm("cvt.rna.tf32.f32 %0, %1;" : "=r"(r) : "f"(f));
    return r;
}
__device__ __forceinline__ void mma_tf32(float* c, const unsigned* a,
                                         unsigned b0, unsigned b1) {
    asm volatile("mma.sync.aligned.m16n8k8.row.col.f32.tf32.tf32.f32 "
                 "{%0,%1,%2,%3}, {%4,%5,%6,%7}, {%8,%9}, {%0,%1,%2,%3};"
                 : "+f"(c[0]), "+f"(c[1]), "+f"(c[2]), "+f"(c[3])
                 : "r"(a[0]), "r"(a[1]), "r"(a[2]), "r"(a[3]), "r"(b0), "r"(b1));
}

// ---- k_prep: weights -> tf32 MMA B-fragment order --------------------------
__global__ void k_prep(const float* __restrict__ w_dcn,
                       const float* __restrict__ w_off,
                       const float* __restrict__ w_mask) {
    int gi = blockIdx.x * 256 + threadIdx.x;
    if (gi < 9 * 1024) {
        int lane = gi & 31;
        int nt = (gi >> 5) & 3, kk = (gi >> 7) & 3, wo = (gi >> 9) & 1, tap = gi >> 10;
        int o = wo * 32 + nt * 8 + (lane >> 2);
        int c = kk * 16 + (lane & 3);
        const float* wp = w_dcn + (o << 6) * 9 + tap;
        g_Bfrag[gi] = make_uint4(tf32c(wp[c * 9]),        tf32c(wp[(c + 4) * 9]),
                                 tf32c(wp[(c + 8) * 9]),  tf32c(wp[(c + 12) * 9]));
    } else if (gi < 9 * 1024 + 9 * 512) {
        int gj = gi - 9 * 1024;
        int lane = gj & 31;
        int nt = (gj >> 5) & 1, kk = (gj >> 6) & 3, wo = (gj >> 8) & 1, tap = gj >> 9;
        int o = wo * 16 + nt * 8 + (lane >> 2);
        int c = kk * 16 + (lane & 3);
        unsigned v[4];
#pragma unroll
        for (int u = 0; u < 4; u++) {
            int cc = c + u * 4;
            float f = (o < 18) ? w_off[(o * 64 + cc) * 9 + tap]
                    : (o < 27) ? w_mask[((o - 18) * 64 + cc) * 9 + tap] : 0.f;
            v[u] = tf32c(f);
        }
        g_Wfrag[gj] = make_uint4(v[0], v[1], v[2], v[3]);
    }
}

// ---- k_main: fused conv + deformable GEMM ----------------------------------
// grid: 1024 blocks (b*128 rows), 256 threads (8 warps: 4 in p x 2 in o)
#define OMT_F 8840                     // 130*68 floats per conv tile
#define OMT_B (OMT_F * 4)              // 35360 B
#define ABUF_B 34816                   // [128p][68f] ping-pong buffer
#define SOM_OFF (2 * ABUF_B)           // 69632: S_om[27][132] floats (14256 B)
#define SMEM_MAIN (3 * OMT_B + 1024)   // 107104 B  (occ 2)

__global__ __launch_bounds__(256, 2)
void k_main(const float* __restrict__ x,
            const float* __restrict__ b_off,
            const float* __restrict__ b_mask,
            const float* __restrict__ b_dcn,
            float* __restrict__ out) {
    __shared__ float sbias_om[32];
    __shared__ float sbias[64];
    extern __shared__ char dsm[];
    char* dgen = (char*)((((uintptr_t)dsm) + 1023) & ~(uintptr_t)1023);
    float* tiles = (float*)dgen;

    const int tid = threadIdx.x;
    const int lane = tid & 31, wid = tid >> 5;
    const int b = blockIdx.x >> 7;
    const int h = blockIdx.x & 127;
    const int hw0 = h << 7;
    const float* xb = x + (b << 20);

    if (tid < 32)
        sbias_om[tid] = (tid < 18) ? b_off[tid] : ((tid < 27) ? b_mask[tid - 18] : 0.f);
    if (tid < 64) sbias[tid] = b_dcn[tid];

    // ===================== phase A: offset/mask conv =====================
    // zero edge rows (w' = 0 and 129) of all 3 tiles
    if (tid < 96) {
        int t3 = tid >> 5, rem = tid & 31;
        int row = (rem >> 4) ? 129 : 0, q = rem & 15;
        *(uint4*)(tiles + t3 * OMT_F + row * 68 + q * 4) = make_uint4(0, 0, 0, 0);
    }
    // stage x rows h-1..h+1 into tiles (row = w+1, col c), tf32
#pragma unroll
    for (int it = 0; it < 2; it++) {
        int T = tid + (it << 8);
        if (T < 384) {
            int di = T >> 7, w = T & 127;
            int gy = h - 1 + di;
            float* dst = tiles + di * OMT_F + (w + 1) * 68;
            if ((unsigned)gy < 128u) {
                const float* xp = xb + (gy << 7) + w;
#pragma unroll
                for (int cg = 0; cg < 16; cg++) {
                    uint4 v;
                    v.x = tf32c(xp[(cg * 4 + 0) << 14]);
                    v.y = tf32c(xp[(cg * 4 + 1) << 14]);
                    v.z = tf32c(xp[(cg * 4 + 2) << 14]);
                    v.w = tf32c(xp[(cg * 4 + 3) << 14]);
                    *(uint4*)(dst + cg * 4) = v;
                }
            } else {
#pragma unroll
                for (int cg = 0; cg < 16; cg++)
                    *(uint4*)(dst + cg * 4) = make_uint4(0, 0, 0, 0);
            }
        }
    }
    __syncthreads();

    // warp tiles: 32p x 16o (conv) / 32p x 32o (dcn)
    const int wp = wid >> 1, wo = wid & 1;
    const int m0 = wp << 5;
    const int r = lane >> 2, t = lane & 3;

    {
        const int o0c = wo << 4;
        float C[2][2][4];
#pragma unroll
        for (int i = 0; i < 2; i++)
#pragma unroll
            for (int j = 0; j < 2; j++)
#pragma unroll
                for (int q = 0; q < 4; q++) C[i][j][q] = 0.f;

#pragma unroll 1
        for (int tp = 0; tp < 9; tp++) {
            const int di = tp / 3, dj = tp - 3 * di;
            const unsigned* tl = (const unsigned*)(tiles + di * OMT_F);
            const uint4* bk = g_Wfrag + ((tp * 2 + wo) << 8) + lane;
#pragma unroll
            for (int kk = 0; kk < 4; kk++) {
                uint4 bf[2];
#pragma unroll
                for (int nt = 0; nt < 2; nt++) bf[nt] = bk[(kk * 2 + nt) << 5];
#pragma unroll
                for (int mt = 0; mt < 2; mt++) {
                    const unsigned* ap = tl + (m0 + mt * 16 + r + dj) * 68 + kk * 16 + t;
                    unsigned A0[4], A1[4];
                    A0[0] = ap[0];  A0[1] = ap[8 * 68];
                    A0[2] = ap[4];  A0[3] = ap[8 * 68 + 4];
                    A1[0] = ap[8];  A1[1] = ap[8 * 68 + 8];
                    A1[2] = ap[12]; A1[3] = ap[8 * 68 + 12];
#pragma unroll
                    for (int nt = 0; nt < 2; nt++) {
                        mma_tf32(C[mt][nt], A0, bf[nt].x, bf[nt].y);
                        mma_tf32(C[mt][nt], A1, bf[nt].z, bf[nt].w);
                    }
                }
            }
        }
        __syncthreads();   // tile reads done before S_om overwrite

        // transpose C -> S_om[27][132] (+bias, sigmoid on mask channels)
        float* Som = (float*)(dgen + SOM_OFF);
        const int prow = lane >> 2;
        const int oc = 2 * (lane & 3);
#pragma unroll
        for (int mt = 0; mt < 2; mt++)
#pragma unroll
            for (int nt = 0; nt < 2; nt++)
#pragma unroll
                for (int q = 0; q < 4; q++) {
                    const int p = m0 + mt * 16 + prow + ((q >> 1) << 3);
                    const int ch = o0c + nt * 8 + oc + (q & 1);
                    if (ch < 27) {
                        float v = C[mt][nt][q] + sbias_om[ch];
                        if (ch >= 18) v = 1.f / (1.f + expf(-v));
                        Som[ch * 132 + p] = v;
                    }
                }
    }
    __syncthreads();   // S_om visible to all; tiles free for ping-pong reuse

    // ===================== phase B: deformable GEMM =====================
    const int o0 = wo << 5;
    const float* Som = (const float*)(dgen + SOM_OFF);

    float C[2][4][4];
#pragma unroll
    for (int i = 0; i < 2; i++)
#pragma unroll
        for (int j = 0; j < 4; j++)
#pragma unroll
            for (int q = 0; q < 4; q++) C[i][j][q] = 0.f;

    const int ps = tid & 127;     // sampling pixel (dup across halves)
    const int c0 = tid >> 7;      // channel half

#pragma unroll 1
    for (int k = 0; k < 9; k++) {
        // bilinear params from SMEM (no sync needed; written in phase A)
        const float dy = Som[(2 * k) * 132 + ps];
        const float dx = Som[(2 * k + 1) * 132 + ps];
        const float m  = Som[(18 + k) * 132 + ps];
        const float py = (float)(h - 1 + k / 3) + dy;
        const float px = (float)(ps - 1 + k % 3) + dx;
        const float y0f = floorf(py), x0f = floorf(px);
        const float wy1 = py - y0f, wx1 = px - x0f;
        const float wy0 = 1.f - wy1, wx0 = 1.f - wx1;
        const int y0 = (int)y0f, x0 = (int)x0f;
        const int y1 = y0 + 1,  x1 = x0 + 1;
        const float vy0 = ((unsigned)y0 < 128u) ? 1.f : 0.f;
        const float vy1 = ((unsigned)y1 < 128u) ? 1.f : 0.f;
        const float vx0 = ((unsigned)x0 < 128u) ? 1.f : 0.f;
        const float vx1 = ((unsigned)x1 < 128u) ? 1.f : 0.f;
        const int y0c = min(max(y0, 0), 127), y1c = min(max(y1, 0), 127);
        const int x0c = min(max(x0, 0), 127), x1c = min(max(x1, 0), 127);
        const float W00 = wy0 * wx0 * m * vy0 * vx0;
        const float W01 = wy0 * wx1 * m * vy0 * vx1;
        const float W10 = wy1 * wx0 * m * vy1 * vx0;
        const float W11 = wy1 * wx1 * m * vy1 * vx1;
        const int o00 = (y0c << 7) + x0c, o01 = (y0c << 7) + x1c;
        const int o10 = (y1c << 7) + x0c, o11 = (y1c << 7) + x1c;

        // sample 32 channels into ping-pong buffer (pad-68, conflict-free STS)
        float* Abuf = (float*)(dgen + (k & 1) * ABUF_B);
#pragma unroll
        for (int g = 0; g < 8; g++) {
            const int c = (c0 << 5) + (g << 2);
            const float* pc = xb + (c << 14);
            uint4 v;
            {
                const float s0 = W00 * pc[o00] + W01 * pc[o01]
                               + W10 * pc[o10] + W11 * pc[o11];
                v.x = tf32c(s0);
            }
            {
                const float* p1 = pc + HW;
                const float s1 = W00 * p1[o00] + W01 * p1[o01]
                               + W10 * p1[o10] + W11 * p1[o11];
                v.y = tf32c(s1);
            }
            {
                const float* p2 = pc + 2 * HW;
                const float s2 = W00 * p2[o00] + W01 * p2[o01]
                               + W10 * p2[o10] + W11 * p2[o11];
                v.z = tf32c(s2);
            }
            {
                const float* p3 = pc + 3 * HW;
                const float s3 = W00 * p3[o00] + W01 * p3[o01]
                               + W10 * p3[o10] + W11 * p3[o11];
                v.w = tf32c(s3);
            }
            *(uint4*)(Abuf + ps * 68 + c) = v;
        }
        __syncthreads();   // the ONLY sync per tap (ping-pong makes 2nd redundant)

        // GEMM: C[32p x 32o] += S[32p x 64c] * W[32o x 64c]^T (tf32)
        const unsigned* Ab = (const unsigned*)(dgen + (k & 1) * ABUF_B);
        const uint4* bk = g_Bfrag + ((k * 2 + wo) << 9) + lane;
#pragma unroll
        for (int kk = 0; kk < 4; kk++) {
            uint4 bf[4];
#pragma unroll
            for (int nt = 0; nt < 4; nt++) bf[nt] = bk[(kk * 4 + nt) << 5];
#pragma unroll
            for (int mt = 0; mt < 2; mt++) {
                const unsigned* ap = Ab + (m0 + mt * 16 + r) * 68 + kk * 16 + t;
                unsigned A0[4], A1[4];
                A0[0] = ap[0];  A0[1] = ap[8 * 68];
                A0[2] = ap[4];  A0[3] = ap[8 * 68 + 4];
                A1[0] = ap[8];  A1[1] = ap[8 * 68 + 8];
                A1[2] = ap[12]; A1[3] = ap[8 * 68 + 12];
#pragma unroll
                for (int nt = 0; nt < 4; nt++) {
                    mma_tf32(C[mt][nt], A0, bf[nt].x, bf[nt].y);
                    mma_tf32(C[mt][nt], A1, bf[nt].z, bf[nt].w);
                }
            }
        }
    }

    // epilogue: transpose to S[64o][132p] (+bias), then coalesced stores
    __syncthreads();
    float* S = (float*)dgen;
    const int prow = lane >> 2;
    const int oc = 2 * (lane & 3);
#pragma unroll
    for (int mt = 0; mt < 2; mt++)
#pragma unroll
        for (int nt = 0; nt < 4; nt++)
#pragma unroll
            for (int q = 0; q < 4; q++) {
                const int p = m0 + mt * 16 + prow + ((q >> 1) << 3);
                const int o = o0 + nt * 8 + oc + (q & 1);
                S[o * 132 + p] = C[mt][nt][q] + sbias[o];
            }
    __syncthreads();
    float* ob = out + (b << 20) + hw0;
#pragma unroll
    for (int j = 0; j < 8; j++) {
        const int f4 = j * 256 + tid;
        const int o = f4 >> 5, p4 = f4 & 31;
        *(float4*)(ob + (o << 14) + p4 * 4) = *(float4*)(S + o * 132 + p4 * 4);
    }
}

// ---------------------------------------------------------------------------
extern "C" void kernel_launch(void* const* d_in, const int* in_sizes, int n_in,
                              void* d_out, int out_size) {
    const float* x      = (const float*)d_in[0];
    const float* w_off  = (const float*)d_in[1];
    const float* b_off  = (const float*)d_in[2];
    const float* w_mask = (const float*)d_in[3];
    const float* b_mask = (const float*)d_in[4];
    const float* w_dcn  = (const float*)d_in[5];
    const float* b_dcn  = (const float*)d_in[6];
    float* out = (float*)d_out;

    cudaFuncSetAttribute(k_main, cudaFuncAttributeMaxDynamicSharedMemorySize, SMEM_MAIN);

    k_prep<<<(9 * 1024 + 9 * 512 + 255) / 256, 256>>>(w_dcn, w_off, w_mask);
    k_main<<<Bb * 128, 256, SMEM_MAIN>>>(x, b_off, b_mask, b_dcn, out);
}